// round 2
// baseline (speedup 1.0000x reference)
#include <cuda_runtime.h>
#include <cstdint>

// Problem constants
#define NB   4096
#define TT   256
#define FF   32
#define HH1  64
#define HH2  32
#define NTO  3
#define BB   32        // batch elements per block
#define NTHR 256
#define NBLK (NB / BB) // 128

// Shared memory layout (floats)
//   sW1[96][256]  layer1 combined weights (k<32: W_ih1, k>=32: W_hh1), columns permuted
//   sW2[96][128]  layer2 combined weights (k<64: W_ih2, k>=64: W_hh2), columns permuted
//   sB1[256], sB2[128]  combined biases, same column permutation
//   sA[128][64]   duplicated activations: rows 0..31 = x_t, 32..95 = h1, 96..127 = h2,
//                 cols store each value twice: sA[k][2b] == sA[k][2b+1]
#define SW1_ELEMS (96 * 256)
#define SW2_ELEMS (96 * 128)
#define SA_OFF    (SW1_ELEMS + SW2_ELEMS + 256 + 128)
#define SMEM_FLOATS (SA_OFF + 128 * 64)
#define SMEM_BYTES  (SMEM_FLOATS * 4)

// Packed fp32x2 FMA (Blackwell FFMA2) — d = a*b + d on two lanes
__device__ __forceinline__ void fma2(uint64_t& d, uint64_t a, uint64_t b) {
    asm("fma.rn.f32x2 %0, %1, %2, %0;" : "+l"(d) : "l"(a), "l"(b));
}
__device__ __forceinline__ float2 u2f2(uint64_t u) {
    float2 f; asm("mov.b64 {%0, %1}, %2;" : "=f"(f.x), "=f"(f.y) : "l"(u)); return f;
}
__device__ __forceinline__ uint64_t f2u2(float x, float y) {
    uint64_t u; asm("mov.b64 %0, {%1, %2};" : "=l"(u) : "f"(x), "f"(y)); return u;
}
__device__ __forceinline__ float sigf(float x) {
    return 1.0f / (1.0f + __expf(-x));
}
__device__ __forceinline__ float tanhx(float x) {
    // tanh(x) = 2*sigmoid(2x) - 1 ; accurate ex2/rcp path (~1e-7 rel), fast
    return 2.0f / (1.0f + __expf(-2.0f * x)) - 1.0f;
}

__global__ void __launch_bounds__(NTHR, 1)
lstm_fused_kernel(const float* __restrict__ x,
                  const float* __restrict__ Wih1, const float* __restrict__ Whh1,
                  const float* __restrict__ bih1, const float* __restrict__ bhh1,
                  const float* __restrict__ Wih2, const float* __restrict__ Whh2,
                  const float* __restrict__ bih2, const float* __restrict__ bhh2,
                  const float* __restrict__ Whead, const float* __restrict__ bhead,
                  float* __restrict__ out)
{
    extern __shared__ float sm[];
    float* sW1 = sm;
    float* sW2 = sW1 + SW1_ELEMS;
    float* sB1 = sW2 + SW2_ELEMS;
    float* sB2 = sB1 + 256;
    float* sA  = sB2 + 128;

    const int tid = threadIdx.x;

    // ---- One-time: load + permute weights into shared ----
    // Column permutation: c = jp*8 + gate*2 + jl, where j = jp*2 + jl.
    // So each 8-float group holds [i_j0,i_j1, f_j0,f_j1, g_j0,g_j1, o_j0,o_j1].
    for (int idx = tid; idx < SW1_ELEMS; idx += NTHR) {
        int k = idx >> 8, c = idx & 255;
        int jp = c >> 3, gate = (c >> 1) & 3, jl = c & 1;
        int g = gate * HH1 + jp * 2 + jl;
        sW1[idx] = (k < FF) ? Wih1[g * FF + k] : Whh1[g * HH1 + (k - FF)];
    }
    for (int idx = tid; idx < SW2_ELEMS; idx += NTHR) {
        int k = idx >> 7, c = idx & 127;
        int jp = c >> 3, gate = (c >> 1) & 3, jl = c & 1;
        int g = gate * HH2 + jp * 2 + jl;
        sW2[idx] = (k < HH1) ? Wih2[g * HH1 + k] : Whh2[g * HH2 + (k - HH1)];
    }
    if (tid < 256) {
        int c = tid;
        int jp = c >> 3, gate = (c >> 1) & 3, jl = c & 1;
        int g = gate * HH1 + jp * 2 + jl;
        sB1[c] = bih1[g] + bhh1[g];
    }
    if (tid < 128) {
        int c = tid;
        int jp = c >> 3, gate = (c >> 1) & 3, jl = c & 1;
        int g = gate * HH2 + jp * 2 + jl;
        sB2[c] = bih2[g] + bhh2[g];
    }
    // Zero h1/h2 rows (rows 32..127)
    for (int idx = tid; idx < 96 * 64; idx += NTHR) sA[32 * 64 + idx] = 0.0f;

    // ---- Thread mappings ----
    // Layer1: 8 b-tiles (4 batch each) x 32 j-pairs = 256 threads
    const int bt1 = tid & 7, jp1 = tid >> 3;
    // Layer2: 16 b-tiles (2 batch each) x 16 j-pairs = 256 threads
    const int bt2 = tid & 15, jp2 = tid >> 4;
    // x loader: 32 batch x 8 float4-chunks
    const int xb = tid >> 3, xf = tid & 7;

    const float* xp = x + ((size_t)(blockIdx.x * BB + xb) * TT) * FF + xf * 4;
    float4 xr = *(const float4*)xp;   // prefetch x_0

    uint64_t c1r[4] = {0, 0, 0, 0};   // cell state layer1: (c_j0,c_j1) per b
    uint64_t c2r[2] = {0, 0};         // cell state layer2

    const float* w1p = sW1 + jp1 * 8;
    const float* a1p = sA  + 8 * bt1;            // cols 2*(4*bt1) .. +7 (4 b's dup)
    const float* w2p = sW2 + jp2 * 8;
    const float* a2p = sA  + 32 * 64 + 4 * bt2;  // rows 32.., cols 2*(2*bt2) .. +3

    for (int t = 0; t < TT; t++) {
        // ---- store x_t duplicated into sA rows 0..31 ----
        {
            float v[4] = {xr.x, xr.y, xr.z, xr.w};
            #pragma unroll
            for (int c = 0; c < 4; c++)
                *(float2*)&sA[(xf * 4 + c) * 64 + 2 * xb] = make_float2(v[c], v[c]);
        }
        if (t + 1 < TT) xr = *(const float4*)(xp + (size_t)(t + 1) * FF);
        __syncthreads();   // S1: x_t + h2_{t-1} visible; everyone past prior reads

        // ---- Layer 1: gates[b][i,f,g,o] packed over (j0,j1) ----
        uint64_t acc[4][4];
        {
            ulonglong2 bA = *(const ulonglong2*)&sB1[jp1 * 8];
            ulonglong2 bBv = *(const ulonglong2*)&sB1[jp1 * 8 + 4];
            #pragma unroll
            for (int b = 0; b < 4; b++) {
                acc[b][0] = bA.x; acc[b][1] = bA.y; acc[b][2] = bBv.x; acc[b][3] = bBv.y;
            }
        }
        #pragma unroll 4
        for (int k = 0; k < 96; k++) {
            ulonglong2 w0 = *(const ulonglong2*)(w1p + k * 256);
            ulonglong2 w1 = *(const ulonglong2*)(w1p + k * 256 + 4);
            ulonglong2 a0 = *(const ulonglong2*)(a1p + k * 64);
            ulonglong2 a1 = *(const ulonglong2*)(a1p + k * 64 + 4);
            uint64_t ab[4] = {a0.x, a0.y, a1.x, a1.y};
            uint64_t wg[4] = {w0.x, w0.y, w1.x, w1.y};
            #pragma unroll
            for (int b = 0; b < 4; b++) {
                #pragma unroll
                for (int g = 0; g < 4; g++) fma2(acc[b][g], ab[b], wg[g]);
            }
        }
        float h1v[4][2];
        #pragma unroll
        for (int b = 0; b < 4; b++) {
            float2 iv = u2f2(acc[b][0]);
            float2 fv = u2f2(acc[b][1]);
            float2 gv = u2f2(acc[b][2]);
            float2 ov = u2f2(acc[b][3]);
            float2 cv = u2f2(c1r[b]);
            float c0 = sigf(fv.x) * cv.x + sigf(iv.x) * tanhx(gv.x);
            float c1 = sigf(fv.y) * cv.y + sigf(iv.y) * tanhx(gv.y);
            c1r[b] = f2u2(c0, c1);
            h1v[b][0] = sigf(ov.x) * tanhx(c0);
            h1v[b][1] = sigf(ov.y) * tanhx(c1);
        }
        __syncthreads();   // S2: all threads done reading h1_{t-1}
        #pragma unroll
        for (int b = 0; b < 4; b++) {
            int col = 2 * (4 * bt1 + b);
            *(float2*)&sA[(32 + jp1 * 2) * 64 + col]     = make_float2(h1v[b][0], h1v[b][0]);
            *(float2*)&sA[(32 + jp1 * 2 + 1) * 64 + col] = make_float2(h1v[b][1], h1v[b][1]);
        }
        __syncthreads();   // S3: h1_t visible

        // ---- Layer 2 ----
        uint64_t acc2[2][4];
        {
            ulonglong2 bA = *(const ulonglong2*)&sB2[jp2 * 8];
            ulonglong2 bBv = *(const ulonglong2*)&sB2[jp2 * 8 + 4];
            #pragma unroll
            for (int b = 0; b < 2; b++) {
                acc2[b][0] = bA.x; acc2[b][1] = bA.y; acc2[b][2] = bBv.x; acc2[b][3] = bBv.y;
            }
        }
        #pragma unroll 4
        for (int k = 0; k < 96; k++) {
            ulonglong2 w0 = *(const ulonglong2*)(w2p + k * 128);
            ulonglong2 w1 = *(const ulonglong2*)(w2p + k * 128 + 4);
            ulonglong2 a0 = *(const ulonglong2*)(a2p + k * 64);
            uint64_t ab[2] = {a0.x, a0.y};
            uint64_t wg[4] = {w0.x, w0.y, w1.x, w1.y};
            #pragma unroll
            for (int b = 0; b < 2; b++) {
                #pragma unroll
                for (int g = 0; g < 4; g++) fma2(acc2[b][g], ab[b], wg[g]);
            }
        }
        float h2v[2][2];
        #pragma unroll
        for (int b = 0; b < 2; b++) {
            float2 iv = u2f2(acc2[b][0]);
            float2 fv = u2f2(acc2[b][1]);
            float2 gv = u2f2(acc2[b][2]);
            float2 ov = u2f2(acc2[b][3]);
            float2 cv = u2f2(c2r[b]);
            float c0 = sigf(fv.x) * cv.x + sigf(iv.x) * tanhx(gv.x);
            float c1 = sigf(fv.y) * cv.y + sigf(iv.y) * tanhx(gv.y);
            c2r[b] = f2u2(c0, c1);
            h2v[b][0] = sigf(ov.x) * tanhx(c0);
            h2v[b][1] = sigf(ov.y) * tanhx(c1);
        }
        __syncthreads();   // S4: all threads done reading h2_{t-1}
        #pragma unroll
        for (int b = 0; b < 2; b++) {
            int col = 2 * (2 * bt2 + b);
            *(float2*)&sA[(96 + jp2 * 2) * 64 + col]     = make_float2(h2v[b][0], h2v[b][0]);
            *(float2*)&sA[(96 + jp2 * 2 + 1) * 64 + col] = make_float2(h2v[b][1], h2v[b][1]);
        }
    }
    __syncthreads();   // final h2 visible

    // ---- Head: out[b][n] = h2[b] . W_head[n] + b_head[n] ----
    if (tid < BB * NTO) {
        int b = tid / NTO, n = tid % NTO;
        float accv = bhead[n];
        #pragma unroll
        for (int j = 0; j < HH2; j++)
            accv += sA[(96 + j) * 64 + 2 * b] * Whead[n * HH2 + j];
        out[(size_t)(blockIdx.x * BB + b) * NTO + n] = accv;
    }
}

extern "C" void kernel_launch(void* const* d_in, const int* in_sizes, int n_in,
                              void* d_out, int out_size) {
    (void)in_sizes; (void)n_in; (void)out_size;
    const float* x     = (const float*)d_in[0];
    const float* Wih1  = (const float*)d_in[1];
    const float* Whh1  = (const float*)d_in[2];
    const float* bih1  = (const float*)d_in[3];
    const float* bhh1  = (const float*)d_in[4];
    const float* Wih2  = (const float*)d_in[5];
    const float* Whh2  = (const float*)d_in[6];
    const float* bih2  = (const float*)d_in[7];
    const float* bhh2  = (const float*)d_in[8];
    const float* Whead = (const float*)d_in[9];
    const float* bhead = (const float*)d_in[10];
    float* out = (float*)d_out;

    cudaFuncSetAttribute(lstm_fused_kernel,
                         cudaFuncAttributeMaxDynamicSharedMemorySize, SMEM_BYTES);
    lstm_fused_kernel<<<NBLK, NTHR, SMEM_BYTES>>>(
        x, Wih1, Whh1, bih1, bhh1, Wih2, Whh2, bih2, bhh2, Whead, bhead, out);
}

// round 3
// speedup vs baseline: 1.7957x; 1.7957x over previous
#include <cuda_runtime.h>
#include <cstdint>

#define TT   256
#define BB   32
#define NTHR 256
#define NBLK 128
#define SA   36    // activation row stride in floats (16B-aligned, bank-staggered)

// shared layout (float offsets)
#define OFF_W1 0                          // [96][256] permuted L1 weights
#define OFF_W2 24576                      // [96][128] permuted L2 weights
#define OFF_B1 36864                      // [256]
#define OFF_B2 37120                      // [128]
#define OFF_X  37248                      // [2][32][SA]
#define OFF_H1 (OFF_X + 2 * 32 * SA)      // [2][64][SA]
#define OFF_H2 (OFF_H1 + 2 * 64 * SA)     // [2][32][SA]
#define SMEM_FLOATS (OFF_H2 + 2 * 32 * SA)
#define SMEM_BYTES  (SMEM_FLOATS * 4)     // 185856 B

__device__ __forceinline__ void fma2(uint64_t& d, uint64_t a, uint64_t b) {
    asm("fma.rn.f32x2 %0, %1, %2, %0;" : "+l"(d) : "l"(a), "l"(b));
}
__device__ __forceinline__ float2 u2f2(uint64_t u) {
    float2 f; asm("mov.b64 {%0, %1}, %2;" : "=f"(f.x), "=f"(f.y) : "l"(u)); return f;
}
__device__ __forceinline__ uint64_t f2u2(float x, float y) {
    uint64_t u; asm("mov.b64 %0, {%1, %2};" : "=l"(u) : "f"(x), "f"(y)); return u;
}
__device__ __forceinline__ float sigf(float x)  { return __fdividef(1.0f, 1.0f + __expf(-x)); }
__device__ __forceinline__ float tanhx(float x) { return __fdividef(2.0f, 1.0f + __expf(-2.0f * x)) - 1.0f; }

// one LSTM cell update for a packed (j0,j1) pair
__device__ __forceinline__ void cellup(uint64_t gi, uint64_t gf, uint64_t gg, uint64_t go,
                                       uint64_t& cst, float2& h) {
    float2 iv = u2f2(gi), fv = u2f2(gf), gv = u2f2(gg), ov = u2f2(go), cv = u2f2(cst);
    float c0 = sigf(fv.x) * cv.x + sigf(iv.x) * tanhx(gv.x);
    float c1 = sigf(fv.y) * cv.y + sigf(iv.y) * tanhx(gv.y);
    cst = f2u2(c0, c1);
    h.x = sigf(ov.x) * tanhx(c0);
    h.y = sigf(ov.y) * tanhx(c1);
}

// L1 k-step: 8 batches, 4 gate-pairs
__device__ __forceinline__ void l1_step(uint64_t (&acc)[8][4], const float* wp, const float* ar) {
    ulonglong2 w01 = *(const ulonglong2*)wp;        // (i-pair, f-pair)
    ulonglong2 w23 = *(const ulonglong2*)(wp + 4);  // (g-pair, o-pair)
    float4 a0 = *(const float4*)ar;
    float4 a1 = *(const float4*)(ar + 4);
    float av[8] = {a0.x, a0.y, a0.z, a0.w, a1.x, a1.y, a1.z, a1.w};
    #pragma unroll
    for (int b = 0; b < 8; b++) {
        uint64_t ad = f2u2(av[b], av[b]);
        fma2(acc[b][0], ad, w01.x); fma2(acc[b][1], ad, w01.y);
        fma2(acc[b][2], ad, w23.x); fma2(acc[b][3], ad, w23.y);
    }
}
// L2 k-step: 4 batches
__device__ __forceinline__ void l2_step(uint64_t (&acc)[4][4], const float* wp, const float* ar) {
    ulonglong2 w01 = *(const ulonglong2*)wp;
    ulonglong2 w23 = *(const ulonglong2*)(wp + 4);
    float4 a0 = *(const float4*)ar;
    float av[4] = {a0.x, a0.y, a0.z, a0.w};
    #pragma unroll
    for (int b = 0; b < 4; b++) {
        uint64_t ad = f2u2(av[b], av[b]);
        fma2(acc[b][0], ad, w01.x); fma2(acc[b][1], ad, w01.y);
        fma2(acc[b][2], ad, w23.x); fma2(acc[b][3], ad, w23.y);
    }
}

__global__ void __launch_bounds__(NTHR, 1)
lstm_pipe_kernel(const float* __restrict__ x,
                 const float* __restrict__ Wih1, const float* __restrict__ Whh1,
                 const float* __restrict__ bih1, const float* __restrict__ bhh1,
                 const float* __restrict__ Wih2, const float* __restrict__ Whh2,
                 const float* __restrict__ bih2, const float* __restrict__ bhh2,
                 const float* __restrict__ Whead, const float* __restrict__ bhead,
                 float* __restrict__ out)
{
    extern __shared__ float sm[];
    const int tid = threadIdx.x;

    // ---- init: permuted weights. col c = jp*8 + gate*2 + jl, j = jp*2 + jl ----
    for (int idx = tid; idx < 96 * 256; idx += NTHR) {
        int k = idx >> 8, c = idx & 255;
        int jp = c >> 3, g = (c >> 1) & 3, jl = c & 1;
        int grow = g * 64 + jp * 2 + jl;
        sm[OFF_W1 + idx] = (k < 32) ? Wih1[grow * 32 + k] : Whh1[grow * 64 + (k - 32)];
    }
    for (int idx = tid; idx < 96 * 128; idx += NTHR) {
        int k = idx >> 7, c = idx & 127;
        int jp = c >> 3, g = (c >> 1) & 3, jl = c & 1;
        int grow = g * 32 + jp * 2 + jl;
        sm[OFF_W2 + idx] = (k < 64) ? Wih2[grow * 64 + k] : Whh2[grow * 32 + (k - 64)];
    }
    {
        int c = tid, jp = c >> 3, g = (c >> 1) & 3, jl = c & 1;
        int grow = g * 64 + jp * 2 + jl;
        sm[OFF_B1 + c] = bih1[grow] + bhh1[grow];
    }
    if (tid < 128) {
        int c = tid, jp = c >> 3, g = (c >> 1) & 3, jl = c & 1;
        int grow = g * 32 + jp * 2 + jl;
        sm[OFF_B2 + c] = bih2[grow] + bhh2[grow];
    }
    for (int idx = tid; idx < 2 * 64 * SA + 2 * 32 * SA; idx += NTHR)
        sm[OFF_H1 + idx] = 0.0f;
    // preload x_0 into sX parity 0
    if (tid < 128) {
        int xb = tid >> 2, xq = tid & 3;
        const float* xg = x + ((size_t)(blockIdx.x * BB + xb) * TT) * 32 + xq * 8;
        float4 v0 = *(const float4*)xg;
        float4 v1 = *(const float4*)(xg + 4);
        float* d = sm + OFF_X;
        int f0 = xq * 8;
        d[(f0 + 0) * SA + xb] = v0.x; d[(f0 + 1) * SA + xb] = v0.y;
        d[(f0 + 2) * SA + xb] = v0.z; d[(f0 + 3) * SA + xb] = v0.w;
        d[(f0 + 4) * SA + xb] = v1.x; d[(f0 + 5) * SA + xb] = v1.y;
        d[(f0 + 6) * SA + xb] = v1.z; d[(f0 + 7) * SA + xb] = v1.w;
    }
    __syncthreads();

    if (tid < 128) {
        // ================= LAYER-1 warps =================
        const int jp = tid & 31;       // lane = jp (coalesced weight loads)
        const int bt = tid >> 5;       // warp -> 8-batch tile
        uint64_t bias[4];
        {
            ulonglong2 b01 = *(const ulonglong2*)(sm + OFF_B1 + jp * 8);
            ulonglong2 b23 = *(const ulonglong2*)(sm + OFF_B1 + jp * 8 + 4);
            bias[0] = b01.x; bias[1] = b01.y; bias[2] = b23.x; bias[3] = b23.y;
        }
        uint64_t c1s[8] = {0,0,0,0,0,0,0,0};

        for (int s = 0; s <= TT; s++) {
            if (s < TT) {
                uint64_t acc[8][4];
                #pragma unroll
                for (int b = 0; b < 8; b++) {
                    acc[b][0] = bias[0]; acc[b][1] = bias[1];
                    acc[b][2] = bias[2]; acc[b][3] = bias[3];
                }
                const float* wp = sm + OFF_W1 + jp * 8;
                const float* ar = sm + OFF_X + (s & 1) * (32 * SA) + 8 * bt;
                #pragma unroll 4
                for (int k = 0; k < 32; k++) { l1_step(acc, wp, ar); wp += 256; ar += SA; }
                ar = sm + OFF_H1 + ((s + 1) & 1) * (64 * SA) + 8 * bt;   // h1_{s-1}
                #pragma unroll 4
                for (int k = 0; k < 64; k++) { l1_step(acc, wp, ar); wp += 256; ar += SA; }

                float2 hv[8];
                #pragma unroll
                for (int b = 0; b < 8; b++)
                    cellup(acc[b][0], acc[b][1], acc[b][2], acc[b][3], c1s[b], hv[b]);

                float* hd = sm + OFF_H1 + (s & 1) * (64 * SA);
                int j0 = 2 * jp;
                *(float4*)&hd[j0 * SA + 8 * bt]           = make_float4(hv[0].x, hv[1].x, hv[2].x, hv[3].x);
                *(float4*)&hd[j0 * SA + 8 * bt + 4]       = make_float4(hv[4].x, hv[5].x, hv[6].x, hv[7].x);
                *(float4*)&hd[(j0 + 1) * SA + 8 * bt]     = make_float4(hv[0].y, hv[1].y, hv[2].y, hv[3].y);
                *(float4*)&hd[(j0 + 1) * SA + 8 * bt + 4] = make_float4(hv[4].y, hv[5].y, hv[6].y, hv[7].y);
            }
            __syncthreads();
        }
    } else {
        // ================= LAYER-2 warps (+ x prefetch) =================
        const int u = tid - 128;
        const int lane = u & 31;
        const int jp = lane & 15;
        const int b0 = (u >> 5) * 8 + (lane >> 4) * 4;
        const int xb = u >> 2, xq = u & 3;
        const float* xg0 = x + ((size_t)(blockIdx.x * BB + xb) * TT) * 32 + xq * 8;
        uint64_t bias[4];
        {
            ulonglong2 b01 = *(const ulonglong2*)(sm + OFF_B2 + jp * 8);
            ulonglong2 b23 = *(const ulonglong2*)(sm + OFF_B2 + jp * 8 + 4);
            bias[0] = b01.x; bias[1] = b01.y; bias[2] = b23.x; bias[3] = b23.y;
        }
        uint64_t c2s[4] = {0,0,0,0};

        for (int s = 0; s <= TT; s++) {
            float4 pv0, pv1;
            const bool dopf = (s + 1 < TT);
            if (dopf) {
                const float* xg = xg0 + (size_t)(s + 1) * 32;
                pv0 = *(const float4*)xg;
                pv1 = *(const float4*)(xg + 4);
            }
            if (s >= 1) {
                uint64_t acc[4][4];
                #pragma unroll
                for (int b = 0; b < 4; b++) {
                    acc[b][0] = bias[0]; acc[b][1] = bias[1];
                    acc[b][2] = bias[2]; acc[b][3] = bias[3];
                }
                const float* wp = sm + OFF_W2 + jp * 8;
                const float* ar = sm + OFF_H1 + ((s + 1) & 1) * (64 * SA) + b0;  // h1_{s-1}
                #pragma unroll 4
                for (int k = 0; k < 64; k++) { l2_step(acc, wp, ar); wp += 128; ar += SA; }
                ar = sm + OFF_H2 + (s & 1) * (32 * SA) + b0;                      // h2_{s-2}
                #pragma unroll 4
                for (int k = 0; k < 32; k++) { l2_step(acc, wp, ar); wp += 128; ar += SA; }

                float2 hv[4];
                #pragma unroll
                for (int b = 0; b < 4; b++)
                    cellup(acc[b][0], acc[b][1], acc[b][2], acc[b][3], c2s[b], hv[b]);

                float* hd = sm + OFF_H2 + ((s + 1) & 1) * (32 * SA);              // h2_{s-1}
                int j0 = 2 * jp;
                *(float4*)&hd[j0 * SA + b0]       = make_float4(hv[0].x, hv[1].x, hv[2].x, hv[3].x);
                *(float4*)&hd[(j0 + 1) * SA + b0] = make_float4(hv[0].y, hv[1].y, hv[2].y, hv[3].y);
            }
            if (dopf) {
                float* d = sm + OFF_X + ((s + 1) & 1) * (32 * SA);
                int f0 = xq * 8;
                d[(f0 + 0) * SA + xb] = pv0.x; d[(f0 + 1) * SA + xb] = pv0.y;
                d[(f0 + 2) * SA + xb] = pv0.z; d[(f0 + 3) * SA + xb] = pv0.w;
                d[(f0 + 4) * SA + xb] = pv1.x; d[(f0 + 5) * SA + xb] = pv1.y;
                d[(f0 + 6) * SA + xb] = pv1.z; d[(f0 + 7) * SA + xb] = pv1.w;
            }
            __syncthreads();
        }
    }

    // ---- head: out[b][n] = h2_{T-1}[b] . W_head[n] + b_head[n] ----
    if (tid < 96) {
        int b = tid / 3, n = tid % 3;
        const float* h2p = sm + OFF_H2 + ((TT - 1) & 1) * (32 * SA);
        float accv = bhead[n];
        #pragma unroll
        for (int j = 0; j < 32; j++)
            accv += h2p[j * SA + b] * Whead[n * 32 + j];
        out[(size_t)(blockIdx.x * BB + b) * 3 + n] = accv;
    }
}

extern "C" void kernel_launch(void* const* d_in, const int* in_sizes, int n_in,
                              void* d_out, int out_size) {
    (void)in_sizes; (void)n_in; (void)out_size;
    const float* x     = (const float*)d_in[0];
    const float* Wih1  = (const float*)d_in[1];
    const float* Whh1  = (const float*)d_in[2];
    const float* bih1  = (const float*)d_in[3];
    const float* bhh1  = (const float*)d_in[4];
    const float* Wih2  = (const float*)d_in[5];
    const float* Whh2  = (const float*)d_in[6];
    const float* bih2  = (const float*)d_in[7];
    const float* bhh2  = (const float*)d_in[8];
    const float* Whead = (const float*)d_in[9];
    const float* bhead = (const float*)d_in[10];
    float* out = (float*)d_out;

    cudaFuncSetAttribute(lstm_pipe_kernel,
                         cudaFuncAttributeMaxDynamicSharedMemorySize, SMEM_BYTES);
    lstm_pipe_kernel<<<NBLK, NTHR, SMEM_BYTES>>>(
        x, Wih1, Whh1, bih1, bhh1, Wih2, Whh2, bih2, bhh2, Whead, bhead, out);
}

// round 4
// speedup vs baseline: 2.1114x; 1.1758x over previous
#include <cuda_runtime.h>
#include <cstdint>

#define TT   256
#define BB   32
#define NTHR 256
#define NBLK 128
#define SA   36    // activation row stride in floats (16B-aligned, bank-staggered)

// shared layout (float offsets)
#define OFF_W1 0                          // [96][256] permuted L1 weights (split halves)
#define OFF_W2 24576                      // [96][128] permuted L2 weights (split halves)
#define OFF_B1 36864                      // [256]
#define OFF_B2 37120                      // [128]
#define OFF_X  37248                      // [2][32][SA]
#define OFF_H1 (OFF_X + 2 * 32 * SA)      // [2][64][SA]
#define OFF_H2 (OFF_H1 + 2 * 64 * SA)     // [2][32][SA]
#define SMEM_FLOATS (OFF_H2 + 2 * 32 * SA)
#define SMEM_BYTES  (SMEM_FLOATS * 4)     // 185856 B

__device__ __forceinline__ void fma2(uint64_t& d, uint64_t a, uint64_t b) {
    asm("fma.rn.f32x2 %0, %1, %2, %0;" : "+l"(d) : "l"(a), "l"(b));
}
__device__ __forceinline__ float2 u2f2(uint64_t u) {
    float2 f; asm("mov.b64 {%0, %1}, %2;" : "=f"(f.x), "=f"(f.y) : "l"(u)); return f;
}
__device__ __forceinline__ uint64_t f2u2(float x, float y) {
    uint64_t u; asm("mov.b64 %0, {%1, %2};" : "=l"(u) : "f"(x), "f"(y)); return u;
}
__device__ __forceinline__ float sigf(float x)  { return __fdividef(1.0f, 1.0f + __expf(-x)); }
__device__ __forceinline__ float tanhx(float x) { return __fdividef(2.0f, 1.0f + __expf(-2.0f * x)) - 1.0f; }

// one LSTM cell update for a packed (j0,j1) pair
__device__ __forceinline__ void cellup(uint64_t gi, uint64_t gf, uint64_t gg, uint64_t go,
                                       uint64_t& cst, float2& h) {
    float2 iv = u2f2(gi), fv = u2f2(gf), gv = u2f2(gg), ov = u2f2(go), cv = u2f2(cst);
    float c0 = sigf(fv.x) * cv.x + sigf(iv.x) * tanhx(gv.x);
    float c1 = sigf(fv.y) * cv.y + sigf(iv.y) * tanhx(gv.y);
    cst = f2u2(c0, c1);
    h.x = sigf(ov.x) * tanhx(c0);
    h.y = sigf(ov.y) * tanhx(c1);
}

// L1 k-step: 8 batches, 4 gate-pairs. wp -> k*256 + jp*4 (i/f half; g/o half at +128)
__device__ __forceinline__ void l1_step(uint64_t (&acc)[8][4], const float* wp, const float* ar) {
    ulonglong2 w01 = *(const ulonglong2*)wp;          // (i0,i1),(f0,f1) — lane-contiguous 16B
    ulonglong2 w23 = *(const ulonglong2*)(wp + 128);  // (g0,g1),(o0,o1)
    float4 a0 = *(const float4*)ar;
    float4 a1 = *(const float4*)(ar + 4);
    float av[8] = {a0.x, a0.y, a0.z, a0.w, a1.x, a1.y, a1.z, a1.w};
    #pragma unroll
    for (int b = 0; b < 8; b++) {
        uint64_t ad = f2u2(av[b], av[b]);
        fma2(acc[b][0], ad, w01.x); fma2(acc[b][1], ad, w01.y);
        fma2(acc[b][2], ad, w23.x); fma2(acc[b][3], ad, w23.y);
    }
}
// L2 k-step: 4 batches. wp -> k*128 + jp*4 (i/f half; g/o half at +64)
__device__ __forceinline__ void l2_step(uint64_t (&acc)[4][4], const float* wp, const float* ar) {
    ulonglong2 w01 = *(const ulonglong2*)wp;
    ulonglong2 w23 = *(const ulonglong2*)(wp + 64);
    float4 a0 = *(const float4*)ar;
    float av[4] = {a0.x, a0.y, a0.z, a0.w};
    #pragma unroll
    for (int b = 0; b < 4; b++) {
        uint64_t ad = f2u2(av[b], av[b]);
        fma2(acc[b][0], ad, w01.x); fma2(acc[b][1], ad, w01.y);
        fma2(acc[b][2], ad, w23.x); fma2(acc[b][3], ad, w23.y);
    }
}

__global__ void __launch_bounds__(NTHR, 1)
lstm_pipe_kernel(const float* __restrict__ x,
                 const float* __restrict__ Wih1, const float* __restrict__ Whh1,
                 const float* __restrict__ bih1, const float* __restrict__ bhh1,
                 const float* __restrict__ Wih2, const float* __restrict__ Whh2,
                 const float* __restrict__ bih2, const float* __restrict__ bhh2,
                 const float* __restrict__ Whead, const float* __restrict__ bhead,
                 float* __restrict__ out)
{
    extern __shared__ float sm[];
    const int tid = threadIdx.x;

    // ---- init: permuted weights, bank-conflict-free split layout ----
    // L1 row k (256 floats): c = (gate>>1)*128 + jp*4 + (gate&1)*2 + jl, j = jp*2+jl
    for (int idx = tid; idx < 96 * 256; idx += NTHR) {
        int k = idx >> 8, c = idx & 255;
        int half = c >> 7, r = c & 127;
        int jp = r >> 2, g2 = (r >> 1) & 1, jl = r & 1;
        int gate = half * 2 + g2;
        int grow = gate * 64 + jp * 2 + jl;
        sm[OFF_W1 + idx] = (k < 32) ? Wih1[grow * 32 + k] : Whh1[grow * 64 + (k - 32)];
    }
    // L2 row k (128 floats): c = (gate>>1)*64 + jp*4 + (gate&1)*2 + jl
    for (int idx = tid; idx < 96 * 128; idx += NTHR) {
        int k = idx >> 7, c = idx & 127;
        int half = c >> 6, r = c & 63;
        int jp = r >> 2, g2 = (r >> 1) & 1, jl = r & 1;
        int gate = half * 2 + g2;
        int grow = gate * 32 + jp * 2 + jl;
        sm[OFF_W2 + idx] = (k < 64) ? Wih2[grow * 64 + k] : Whh2[grow * 32 + (k - 64)];
    }
    {   // biases keep the acc-register order: c = jp*8 + gate*2 + jl
        int c = tid, jp = c >> 3, g = (c >> 1) & 3, jl = c & 1;
        int grow = g * 64 + jp * 2 + jl;
        sm[OFF_B1 + c] = bih1[grow] + bhh1[grow];
    }
    if (tid < 128) {
        int c = tid, jp = c >> 3, g = (c >> 1) & 3, jl = c & 1;
        int grow = g * 32 + jp * 2 + jl;
        sm[OFF_B2 + c] = bih2[grow] + bhh2[grow];
    }
    for (int idx = tid; idx < 2 * 64 * SA + 2 * 32 * SA; idx += NTHR)
        sm[OFF_H1 + idx] = 0.0f;
    // preload x_0 into sX parity 0
    if (tid < 128) {
        int xb = tid >> 2, xq = tid & 3;
        const float* xg = x + ((size_t)(blockIdx.x * BB + xb) * TT) * 32 + xq * 8;
        float4 v0 = *(const float4*)xg;
        float4 v1 = *(const float4*)(xg + 4);
        float* d = sm + OFF_X;
        int f0 = xq * 8;
        d[(f0 + 0) * SA + xb] = v0.x; d[(f0 + 1) * SA + xb] = v0.y;
        d[(f0 + 2) * SA + xb] = v0.z; d[(f0 + 3) * SA + xb] = v0.w;
        d[(f0 + 4) * SA + xb] = v1.x; d[(f0 + 5) * SA + xb] = v1.y;
        d[(f0 + 6) * SA + xb] = v1.z; d[(f0 + 7) * SA + xb] = v1.w;
    }
    __syncthreads();

    if (tid < 128) {
        // ================= LAYER-1 warps =================
        const int jp = tid & 31;       // lane = jp: weight LDS.128 lane-contiguous
        const int bt = tid >> 5;       // warp -> 8-batch tile
        uint64_t bias[4];
        {
            ulonglong2 b01 = *(const ulonglong2*)(sm + OFF_B1 + jp * 8);
            ulonglong2 b23 = *(const ulonglong2*)(sm + OFF_B1 + jp * 8 + 4);
            bias[0] = b01.x; bias[1] = b01.y; bias[2] = b23.x; bias[3] = b23.y;
        }
        uint64_t c1s[8] = {0,0,0,0,0,0,0,0};

        for (int s = 0; s <= TT; s++) {
            if (s < TT) {
                uint64_t acc[8][4];
                #pragma unroll
                for (int b = 0; b < 8; b++) {
                    acc[b][0] = bias[0]; acc[b][1] = bias[1];
                    acc[b][2] = bias[2]; acc[b][3] = bias[3];
                }
                const float* wp = sm + OFF_W1 + jp * 4;
                const float* ar = sm + OFF_X + (s & 1) * (32 * SA) + 8 * bt;
                #pragma unroll 4
                for (int k = 0; k < 32; k++) { l1_step(acc, wp, ar); wp += 256; ar += SA; }
                ar = sm + OFF_H1 + ((s + 1) & 1) * (64 * SA) + 8 * bt;   // h1_{s-1}
                #pragma unroll 4
                for (int k = 0; k < 64; k++) { l1_step(acc, wp, ar); wp += 256; ar += SA; }

                float2 hv[8];
                #pragma unroll
                for (int b = 0; b < 8; b++)
                    cellup(acc[b][0], acc[b][1], acc[b][2], acc[b][3], c1s[b], hv[b]);

                float* hd = sm + OFF_H1 + (s & 1) * (64 * SA);
                int j0 = 2 * jp;
                *(float4*)&hd[j0 * SA + 8 * bt]           = make_float4(hv[0].x, hv[1].x, hv[2].x, hv[3].x);
                *(float4*)&hd[j0 * SA + 8 * bt + 4]       = make_float4(hv[4].x, hv[5].x, hv[6].x, hv[7].x);
                *(float4*)&hd[(j0 + 1) * SA + 8 * bt]     = make_float4(hv[0].y, hv[1].y, hv[2].y, hv[3].y);
                *(float4*)&hd[(j0 + 1) * SA + 8 * bt + 4] = make_float4(hv[4].y, hv[5].y, hv[6].y, hv[7].y);
            }
            __syncthreads();
        }
    } else {
        // ================= LAYER-2 warps (+ x prefetch) =================
        const int u = tid - 128;
        const int lane = u & 31;
        const int jp = lane & 15;
        const int b0 = (u >> 5) * 8 + (lane >> 4) * 4;
        const int xb = u >> 2, xq = u & 3;
        const float* xg0 = x + ((size_t)(blockIdx.x * BB + xb) * TT) * 32 + xq * 8;
        uint64_t bias[4];
        {
            ulonglong2 b01 = *(const ulonglong2*)(sm + OFF_B2 + jp * 8);
            ulonglong2 b23 = *(const ulonglong2*)(sm + OFF_B2 + jp * 8 + 4);
            bias[0] = b01.x; bias[1] = b01.y; bias[2] = b23.x; bias[3] = b23.y;
        }
        uint64_t c2s[4] = {0,0,0,0};

        for (int s = 0; s <= TT; s++) {
            float4 pv0, pv1;
            const bool dopf = (s + 1 < TT);
            if (dopf) {
                const float* xg = xg0 + (size_t)(s + 1) * 32;
                pv0 = *(const float4*)xg;
                pv1 = *(const float4*)(xg + 4);
            }
            if (s >= 1) {
                uint64_t acc[4][4];
                #pragma unroll
                for (int b = 0; b < 4; b++) {
                    acc[b][0] = bias[0]; acc[b][1] = bias[1];
                    acc[b][2] = bias[2]; acc[b][3] = bias[3];
                }
                const float* wp = sm + OFF_W2 + jp * 4;
                const float* ar = sm + OFF_H1 + ((s + 1) & 1) * (64 * SA) + b0;  // h1_{s-1}
                #pragma unroll 4
                for (int k = 0; k < 64; k++) { l2_step(acc, wp, ar); wp += 128; ar += SA; }
                ar = sm + OFF_H2 + (s & 1) * (32 * SA) + b0;                      // h2_{s-2}
                #pragma unroll 4
                for (int k = 0; k < 32; k++) { l2_step(acc, wp, ar); wp += 128; ar += SA; }

                float2 hv[4];
                #pragma unroll
                for (int b = 0; b < 4; b++)
                    cellup(acc[b][0], acc[b][1], acc[b][2], acc[b][3], c2s[b], hv[b]);

                float* hd = sm + OFF_H2 + ((s + 1) & 1) * (32 * SA);              // h2_{s-1}
                int j0 = 2 * jp;
                *(float4*)&hd[j0 * SA + b0]       = make_float4(hv[0].x, hv[1].x, hv[2].x, hv[3].x);
                *(float4*)&hd[(j0 + 1) * SA + b0] = make_float4(hv[0].y, hv[1].y, hv[2].y, hv[3].y);
            }
            if (dopf) {
                float* d = sm + OFF_X + ((s + 1) & 1) * (32 * SA);
                int f0 = xq * 8;
                d[(f0 + 0) * SA + xb] = pv0.x; d[(f0 + 1) * SA + xb] = pv0.y;
                d[(f0 + 2) * SA + xb] = pv0.z; d[(f0 + 3) * SA + xb] = pv0.w;
                d[(f0 + 4) * SA + xb] = pv1.x; d[(f0 + 5) * SA + xb] = pv1.y;
                d[(f0 + 6) * SA + xb] = pv1.z; d[(f0 + 7) * SA + xb] = pv1.w;
            }
            __syncthreads();
        }
    }

    // ---- head: out[b][n] = h2_{T-1}[b] . W_head[n] + b_head[n] ----
    if (tid < 96) {
        int b = tid / 3, n = tid % 3;
        const float* h2p = sm + OFF_H2 + ((TT - 1) & 1) * (32 * SA);
        float accv = bhead[n];
        #pragma unroll
        for (int j = 0; j < 32; j++)
            accv += h2p[j * SA + b] * Whead[n * 32 + j];
        out[(size_t)(blockIdx.x * BB + b) * 3 + n] = accv;
    }
}

extern "C" void kernel_launch(void* const* d_in, const int* in_sizes, int n_in,
                              void* d_out, int out_size) {
    (void)in_sizes; (void)n_in; (void)out_size;
    const float* x     = (const float*)d_in[0];
    const float* Wih1  = (const float*)d_in[1];
    const float* Whh1  = (const float*)d_in[2];
    const float* bih1  = (const float*)d_in[3];
    const float* bhh1  = (const float*)d_in[4];
    const float* Wih2  = (const float*)d_in[5];
    const float* Whh2  = (const float*)d_in[6];
    const float* bih2  = (const float*)d_in[7];
    const float* bhh2  = (const float*)d_in[8];
    const float* Whead = (const float*)d_in[9];
    const float* bhead = (const float*)d_in[10];
    float* out = (float*)d_out;

    cudaFuncSetAttribute(lstm_pipe_kernel,
                         cudaFuncAttributeMaxDynamicSharedMemorySize, SMEM_BYTES);
    lstm_pipe_kernel<<<NBLK, NTHR, SMEM_BYTES>>>(
        x, Wih1, Whh1, bih1, bhh1, Wih2, Whh2, bih2, bhh2, Whead, bhead, out);
}